// round 16
// baseline (speedup 1.0000x reference)
#include <cuda_runtime.h>
#include <cuda_fp16.h>
#include <cuda_fp8.h>
#include <stdint.h>
#include <math.h>

#define FF 32
#define BB 2048
#define KK 64
#define HH 64
#define NPAIR 496
#define NTHREADS 256
#define SLOTS 512
#define VSTRIDE 66   // f16 elems per sV row (132B); 32-bit loads only (4B-aligned)

__device__ __align__(16) unsigned char gW8[HH * 64]; // fp8 W, lane-packed
__device__ __align__(16) unsigned      gPij[SLOTS];  // (rowOffJ<<16)|rowOffI

__device__ __forceinline__ unsigned short cvt_e4m3x2_f16x2(__half2 v)
{
    unsigned short r;
    asm("cvt.rn.satfinite.e4m3x2.f16x2 %0, %1;" : "=h"(r) : "r"(*(unsigned*)&v));
    return r;
}
__device__ __forceinline__ __half2 cvt_f16x2_e4m3x2(unsigned short v)
{
    unsigned r;
    asm("cvt.rn.f16x2.e4m3x2 %0, %1;" : "=r"(r) : "h"(v));
    return *(__half2*)&r;
}
// pack two f32 into half2: lo = a, hi = b
__device__ __forceinline__ __half2 pack_h2_f32(float lo, float hi)
{
    unsigned r;
    asm("cvt.rn.f16x2.f32 %0, %1, %2;" : "=r"(r) : "f"(hi), "f"(lo));
    return *(__half2*)&r;
}
__device__ __forceinline__ void mma_e4m3(float* c,
                                         unsigned a0, unsigned a1,
                                         unsigned a2, unsigned a3,
                                         unsigned b0, unsigned b1)
{
    asm volatile(
        "mma.sync.aligned.m16n8k32.row.col.f32.e4m3.e4m3.f32 "
        "{%0,%1,%2,%3}, {%4,%5,%6,%7}, {%8,%9}, {%0,%1,%2,%3};\n"
        : "+f"(c[0]), "+f"(c[1]), "+f"(c[2]), "+f"(c[3])
        : "r"(a0), "r"(a1), "r"(a2), "r"(a3), "r"(b0), "r"(b1));
}
// 32-bit loads only: rows are 4B-aligned (132B stride), NOT 8B-aligned.
__device__ __forceinline__ unsigned buildA(const __half* vh, int eI, int eJ, int koff)
{
    unsigned vi0 = *(const unsigned*)(vh + eI + koff);
    unsigned vi1 = *(const unsigned*)(vh + eI + koff + 2);
    unsigned vj0 = *(const unsigned*)(vh + eJ + koff);
    unsigned vj1 = *(const unsigned*)(vh + eJ + koff + 2);
    __half2 p0 = __hmul2(*(__half2*)&vi0, *(__half2*)&vj0);
    __half2 p1 = __hmul2(*(__half2*)&vi1, *(__half2*)&vj1);
    unsigned short lo = cvt_e4m3x2_f16x2(p0);   // bytes k0,k1
    unsigned short hi = cvt_e4m3x2_f16x2(p1);   // bytes k2,k3
    unsigned r;
    asm("mov.b32 %0, {%1, %2};" : "=r"(r) : "h"(lo), "h"(hi));
    return r;
}
__device__ __forceinline__ __half2 shfl_xor_h2(__half2 v, int m)
{
    unsigned u = __shfl_xor_sync(0xffffffffu, *(unsigned*)&v, m);
    return *(__half2*)&u;
}

// One-shot precompute: fp8 W (x64, lane-packed) + pair table.
// W byte layout: (k,h) at h*64 + ((k>>2)&3)*16 + (k>>4)*4 + (k&3)
__global__ void afm_init(const float* __restrict__ at_w)
{
    int idx = blockIdx.x * blockDim.x + threadIdx.x;
    if (idx < KK * HH) {
        int k = idx >> 6, h = idx & 63;
        int seg = k >> 4, c = (k >> 2) & 3, by = k & 3;
        __nv_fp8_storage_t f8 = __nv_cvt_float_to_fp8(
            at_w[idx] * 64.0f, __NV_SATFINITE, __NV_E4M3);
        gW8[h * 64 + c * 16 + seg * 4 + by] = (unsigned char)f8;
    }
    if (idx < SLOTS) {
        unsigned v = 0;
        if (idx < NPAIR) {
            int i = 0, rem = idx;
            while (rem >= FF - 1 - i) { rem -= FF - 1 - i; i++; }
            int j = i + 1 + rem;
            v = ((unsigned)(j * VSTRIDE) << 16) | (unsigned)(i * VSTRIDE);
        }
        gPij[idx] = v;
    }
}

__global__ __launch_bounds__(NTHREADS, 4) void afm_kernel(
    const int* __restrict__ x, const float* __restrict__ emb,
    const float* __restrict__ at_b,
    const float* __restrict__ at_h, const float* __restrict__ pvec,
    const float* __restrict__ w0, const float* __restrict__ w1,
    float* __restrict__ out)
{
    __shared__ __align__(16) __half sVh[FF * VSTRIDE];       // ~4.2 KB, V*16
    __shared__ __align__(16) unsigned char sW8[HH * 64];     // 4 KB fp8 W*64
    __shared__ __half2 sAbh[HH / 2];                         // bias*2^14, half2
    __shared__ __half2 sAhh[HH / 2];                         // at_h, half2
    __shared__ float sPooled[KK];
    __shared__ __align__(16) unsigned sPij[SLOTS];
    __shared__ int   sX[FF];
    __shared__ float sFm1;

    const int b   = blockIdx.x;
    const int tid = threadIdx.x;
    const int w   = tid >> 5;
    const int L   = tid & 31;
    const int c   = L & 3;
    const int qr  = L >> 2;

    if (tid < FF) sX[tid] = x[tid * BB + b];
    if (tid < KK) sPooled[tid] = 0.f;
    if (tid < HH / 2) {
        sAbh[tid] = pack_h2_f32(at_b[2 * tid] * 16384.0f,
                                at_b[2 * tid + 1] * 16384.0f);
        sAhh[tid] = pack_h2_f32(at_h[2 * tid], at_h[2 * tid + 1]);
    }
    ((uint2*)sPij)[tid] = ((const uint2*)gPij)[tid];
    ((uint4*)sW8)[tid]  = ((const uint4*)gW8)[tid];   // 4 KB = 256 uint4
    __syncthreads();

    // gather embedding rows -> f16 * 16 (coalesced along k)
    for (int idx = tid; idx < FF * KK; idx += NTHREADS) {
        int f = idx >> 6, k = idx & 63;
        sVh[f * VSTRIDE + k] = __float2half(emb[(long)sX[f] * KK + k] * 16.0f);
    }
    __syncthreads();

    // first-order FM part
    if (w == 0) {
        float v = w1[sX[L]];
        #pragma unroll
        for (int off = 16; off; off >>= 1) v += __shfl_xor_sync(0xffffffffu, v, off);
        if (L == 0) sFm1 = v + w0[0];
    }

    const __half* const vh = sVh;
    const unsigned char* const wb = sW8 + (qr << 6) + (c << 4); // lane B base
    const int kb = c << 2;  // 4c

    // register-resident epilogue coefficients: h-pair (nt*8+2c, +1)
    __half2 abh[8], ahh[8];
    #pragma unroll
    for (int nt = 0; nt < 8; nt++) {
        abh[nt] = sAbh[nt * 4 + c];
        ahh[nt] = sAhh[nt * 4 + c];
    }

    // half2 pooled accumulators: pk2[seg*2+r] = {k, k+1}, k = 4c+16seg+2r
    __half2 pk2[8];
    #pragma unroll
    for (int t = 0; t < 8; t++) pk2[t] = __float2half2_rn(0.f);
    const __half2 zero2 = __float2half2_rn(0.f);

    // ---- MMA + fused epilogue/pooling -------------------------------------
    #pragma unroll 1
    for (int it = 0; it < 4; it++) {
        const int mbase = (w * 4 + it) << 4;
        const int p0 = mbase + qr, p1 = p0 + 8;
        const unsigned pij0 = sPij[p0], pij1 = sPij[p1];
        const int eI0 = pij0 & 0xffffu, eJ0 = pij0 >> 16;
        const int eI1 = pij1 & 0xffffu, eJ1 = pij1 >> 16;

        // A fragments (fp8): fa[u][0]=p0 k, [1]=p1 k, [2]=p0 k+16, [3]=p1 k+16
        unsigned fa[2][4];
        #pragma unroll
        for (int u = 0; u < 2; u++) {
            int k0 = kb + (u << 5);
            fa[u][0] = buildA(vh, eI0, eJ0, k0);
            fa[u][1] = buildA(vh, eI1, eJ1, k0);
            fa[u][2] = buildA(vh, eI0, eJ0, k0 + 16);
            fa[u][3] = buildA(vh, eI1, eJ1, k0 + 16);
        }

        __half2 s0h = zero2, s1h = zero2;
        #pragma unroll
        for (int nt = 0; nt < 8; nt++) {
            uint4 bb = *(const uint4*)(wb + (nt << 9));   // 4 B regs, 1 LDS.128
            float acc[4] = {0.f, 0.f, 0.f, 0.f};
            mma_e4m3(acc, fa[0][0], fa[0][1], fa[0][2], fa[0][3], bb.x, bb.y);
            mma_e4m3(acc, fa[1][0], fa[1][1], fa[1][2], fa[1][3], bb.z, bb.w);

            __half2 a01 = pack_h2_f32(acc[0], acc[1]);   // p0: h even/odd
            __half2 a23 = pack_h2_f32(acc[2], acc[3]);   // p1
            a01 = __hmax2(__hadd2(a01, abh[nt]), zero2);
            a23 = __hmax2(__hadd2(a23, abh[nt]), zero2);
            s0h = __hfma2(a01, ahh[nt], s0h);
            s1h = __hfma2(a23, ahh[nt], s1h);
        }
        // quad reduce in half2, then collapse to float + descale 2^-14
        s0h = __hadd2(s0h, shfl_xor_h2(s0h, 1));
        s0h = __hadd2(s0h, shfl_xor_h2(s0h, 2));
        s1h = __hadd2(s1h, shfl_xor_h2(s1h, 1));
        s1h = __hadd2(s1h, shfl_xor_h2(s1h, 2));
        float s0 = __low2float(s0h) + __high2float(s0h);
        float s1 = __low2float(s1h) + __high2float(s1h);
        s0 = (p0 < NPAIR) ? s0 * 6.103515625e-05f : 0.f;
        s1 = (p1 < NPAIR) ? s1 * 6.103515625e-05f : 0.f;

        // fused pooling from fp8 A regs (VV*256), accumulate in half2
        __half2 s0b = __half2half2(__float2half_rn(s0));
        __half2 s1b = __half2half2(__float2half_rn(s1));
        #pragma unroll
        for (int u = 0; u < 2; u++) {
            int sA = (u << 1) << 1;        // pk index base for seg 2u
            int sB = ((u << 1) + 1) << 1;  // seg 2u+1
            pk2[sA]     = __hfma2(cvt_f16x2_e4m3x2((unsigned short)(fa[u][0] & 0xffffu)), s0b, pk2[sA]);
            pk2[sA + 1] = __hfma2(cvt_f16x2_e4m3x2((unsigned short)(fa[u][0] >> 16)),     s0b, pk2[sA + 1]);
            pk2[sA]     = __hfma2(cvt_f16x2_e4m3x2((unsigned short)(fa[u][1] & 0xffffu)), s1b, pk2[sA]);
            pk2[sA + 1] = __hfma2(cvt_f16x2_e4m3x2((unsigned short)(fa[u][1] >> 16)),     s1b, pk2[sA + 1]);
            pk2[sB]     = __hfma2(cvt_f16x2_e4m3x2((unsigned short)(fa[u][2] & 0xffffu)), s0b, pk2[sB]);
            pk2[sB + 1] = __hfma2(cvt_f16x2_e4m3x2((unsigned short)(fa[u][2] >> 16)),     s0b, pk2[sB + 1]);
            pk2[sB]     = __hfma2(cvt_f16x2_e4m3x2((unsigned short)(fa[u][3] & 0xffffu)), s1b, pk2[sB]);
            pk2[sB + 1] = __hfma2(cvt_f16x2_e4m3x2((unsigned short)(fa[u][3] >> 16)),     s1b, pk2[sB + 1]);
        }
    }

    // reduce pooled over qr lanes, then atomics from lanes 0-3
    #pragma unroll
    for (int t = 0; t < 8; t++) {
        __half2 v = pk2[t];
        v = __hadd2(v, shfl_xor_h2(v, 4));
        v = __hadd2(v, shfl_xor_h2(v, 8));
        v = __hadd2(v, shfl_xor_h2(v, 16));
        pk2[t] = v;
    }
    if (L < 4) {
        #pragma unroll
        for (int s = 0; s < 4; s++)
            #pragma unroll
            for (int r = 0; r < 2; r++) {
                float2 f = __half22float2(pk2[s * 2 + r]);
                int k0 = (L << 2) + (s << 4) + (r << 1);
                atomicAdd(&sPooled[k0],     f.x);
                atomicAdd(&sPooled[k0 + 1], f.y);
            }
    }
    __syncthreads();

    if (w == 0) {
        float2 pv = ((const float2*)pvec)[L];
        float d = sPooled[2 * L] * pv.x + sPooled[2 * L + 1] * pv.y;
        #pragma unroll
        for (int off = 16; off; off >>= 1) d += __shfl_xor_sync(0xffffffffu, d, off);
        if (L == 0) {
            float logit = d * 0.00390625f + sFm1;   // 2^-8 descale
            out[b] = 1.f / (1.f + expf(-logit));
        }
    }
}

extern "C" void kernel_launch(void* const* d_in, const int* in_sizes, int n_in,
                              void* d_out, int out_size) {
    (void)in_sizes; (void)n_in; (void)out_size;
    const int*   x    = (const int*)  d_in[0];
    const float* emb  = (const float*)d_in[1];
    const float* at_w = (const float*)d_in[2];
    const float* at_b = (const float*)d_in[3];
    const float* at_h = (const float*)d_in[4];
    const float* pvec = (const float*)d_in[5];
    const float* w0   = (const float*)d_in[6];
    const float* w1   = (const float*)d_in[7];
    float* out = (float*)d_out;

    afm_init<<<16, 256>>>(at_w);
    afm_kernel<<<BB, NTHREADS>>>(x, emb, at_b, at_h, pvec, w0, w1, out);
}

// round 17
// speedup vs baseline: 1.0848x; 1.0848x over previous
#include <cuda_runtime.h>
#include <cuda_fp16.h>
#include <cuda_fp8.h>
#include <stdint.h>
#include <math.h>

#define FF 32
#define BB 2048
#define KK 64
#define HH 64
#define NPAIR 496
#define NTHREADS 256
#define SLOTS 512
#define VSTRIDE 68   // f16 elems per sV row (136B): 8B-aligned rows, 2i bank shift

__device__ __align__(16) unsigned char gW8[HH * 64]; // fp8 W, lane-packed
__device__ __align__(16) unsigned      gPij[SLOTS];  // (rowOffJ<<16)|rowOffI

__device__ __forceinline__ unsigned short cvt_e4m3x2_f16x2(__half2 v)
{
    unsigned short r;
    asm("cvt.rn.satfinite.e4m3x2.f16x2 %0, %1;" : "=h"(r) : "r"(*(unsigned*)&v));
    return r;
}
__device__ __forceinline__ __half2 cvt_f16x2_e4m3x2(unsigned short v)
{
    unsigned r;
    asm("cvt.rn.f16x2.e4m3x2 %0, %1;" : "=r"(r) : "h"(v));
    return *(__half2*)&r;
}
__device__ __forceinline__ void mma_e4m3(float* c,
                                         unsigned a0, unsigned a1,
                                         unsigned a2, unsigned a3,
                                         unsigned b0, unsigned b1)
{
    asm volatile(
        "mma.sync.aligned.m16n8k32.row.col.f32.e4m3.e4m3.f32 "
        "{%0,%1,%2,%3}, {%4,%5,%6,%7}, {%8,%9}, {%0,%1,%2,%3};\n"
        : "+f"(c[0]), "+f"(c[1]), "+f"(c[2]), "+f"(c[3])
        : "r"(a0), "r"(a1), "r"(a2), "r"(a3), "r"(b0), "r"(b1));
}
// rows are 8B-aligned with VSTRIDE=68 (136B); koff*2 is a multiple of 8.
__device__ __forceinline__ unsigned buildA(const __half* vh, int eI, int eJ, int koff)
{
    uint2 vi = *(const uint2*)(vh + eI + koff);
    uint2 vj = *(const uint2*)(vh + eJ + koff);
    __half2 p0 = __hmul2(*(__half2*)&vi.x, *(__half2*)&vj.x);
    __half2 p1 = __hmul2(*(__half2*)&vi.y, *(__half2*)&vj.y);
    unsigned short lo = cvt_e4m3x2_f16x2(p0);   // bytes k0,k1
    unsigned short hi = cvt_e4m3x2_f16x2(p1);   // bytes k2,k3
    unsigned r;
    asm("mov.b32 %0, {%1, %2};" : "=r"(r) : "h"(lo), "h"(hi));
    return r;
}
__device__ __forceinline__ __half2 shfl_xor_h2(__half2 v, int m)
{
    unsigned u = __shfl_xor_sync(0xffffffffu, *(unsigned*)&v, m);
    return *(__half2*)&u;
}

// One-shot precompute: fp8 W (x64, lane-packed) + pair table.
// W byte layout: (k,h) at h*64 + ((k>>2)&3)*16 + (k>>4)*4 + (k&3)
// so lane (n=h%8, c) LDS.128 at h*64+c*16 yields {b0u0, b1u0, b0u1, b1u1}.
__global__ void afm_init(const float* __restrict__ at_w)
{
    int idx = blockIdx.x * blockDim.x + threadIdx.x;
    if (idx < KK * HH) {
        int k = idx >> 6, h = idx & 63;
        int seg = k >> 4, c = (k >> 2) & 3, by = k & 3;
        __nv_fp8_storage_t f8 = __nv_cvt_float_to_fp8(
            at_w[idx] * 64.0f, __NV_SATFINITE, __NV_E4M3);
        gW8[h * 64 + c * 16 + seg * 4 + by] = (unsigned char)f8;
    }
    if (idx < SLOTS) {
        unsigned v = 0;
        if (idx < NPAIR) {
            int i = 0, rem = idx;
            while (rem >= FF - 1 - i) { rem -= FF - 1 - i; i++; }
            int j = i + 1 + rem;
            v = ((unsigned)(j * VSTRIDE) << 16) | (unsigned)(i * VSTRIDE);
        }
        gPij[idx] = v;
    }
}

__global__ __launch_bounds__(NTHREADS, 4) void afm_kernel(
    const int* __restrict__ x, const float* __restrict__ emb,
    const float* __restrict__ at_b,
    const float* __restrict__ at_h, const float* __restrict__ pvec,
    const float* __restrict__ w0, const float* __restrict__ w1,
    float* __restrict__ out)
{
    __shared__ __align__(16) __half sVh[FF * VSTRIDE];       // ~4.25 KB, V*16
    __shared__ __align__(16) unsigned char sW8[HH * 64];     // 4 KB fp8 W*64
    __shared__ float sAth[HH];
    __shared__ float sAb[HH];                                // bias * 2^14
    __shared__ float sPooled[KK];
    __shared__ __align__(16) unsigned sPij[SLOTS];
    __shared__ int   sX[FF];
    __shared__ float sFm1;

    const int b   = blockIdx.x;
    const int tid = threadIdx.x;
    const int w   = tid >> 5;
    const int L   = tid & 31;
    const int c   = L & 3;
    const int qr  = L >> 2;

    if (tid < FF) sX[tid] = x[tid * BB + b];
    if (tid < KK) {
        sPooled[tid] = 0.f;
        sAth[tid]    = at_h[tid];
        sAb[tid]     = at_b[tid] * 16384.0f;   // 2^14 pre-scale
    }
    ((uint2*)sPij)[tid] = ((const uint2*)gPij)[tid];
    ((uint4*)sW8)[tid]  = ((const uint4*)gW8)[tid];   // 4 KB = 256 uint4
    __syncthreads();

    // gather embedding rows -> f16 * 16 (coalesced along k)
    for (int idx = tid; idx < FF * KK; idx += NTHREADS) {
        int f = idx >> 6, k = idx & 63;
        sVh[f * VSTRIDE + k] = __float2half(emb[(long)sX[f] * KK + k] * 16.0f);
    }
    __syncthreads();

    // first-order FM part
    if (w == 0) {
        float v = w1[sX[L]];
        #pragma unroll
        for (int off = 16; off; off >>= 1) v += __shfl_xor_sync(0xffffffffu, v, off);
        if (L == 0) sFm1 = v + w0[0];
    }

    const __half* const vh = sVh;
    const unsigned char* const wb = sW8 + (qr << 6) + (c << 4); // lane B base
    const int kb = c << 2;  // 4c

    // half2 pooled accumulators: pk2[seg*2+r] = {k, k+1}, k = 4c+16seg+2r
    __half2 pk2[8];
    #pragma unroll
    for (int t = 0; t < 8; t++) pk2[t] = __float2half2_rn(0.f);

    // ---- MMA + fused epilogue/pooling -------------------------------------
    #pragma unroll 1
    for (int it = 0; it < 4; it++) {
        const int mbase = (w * 4 + it) << 4;
        const int p0 = mbase + qr, p1 = p0 + 8;
        const unsigned pij0 = sPij[p0], pij1 = sPij[p1];
        const int eI0 = pij0 & 0xffffu, eJ0 = pij0 >> 16;
        const int eI1 = pij1 & 0xffffu, eJ1 = pij1 >> 16;

        // A fragments (fp8): fa[u][0]=p0 k, [1]=p1 k, [2]=p0 k+16, [3]=p1 k+16
        unsigned fa[2][4];
        #pragma unroll
        for (int u = 0; u < 2; u++) {
            int k0 = kb + (u << 5);
            fa[u][0] = buildA(vh, eI0, eJ0, k0);
            fa[u][1] = buildA(vh, eI1, eJ1, k0);
            fa[u][2] = buildA(vh, eI0, eJ0, k0 + 16);
            fa[u][3] = buildA(vh, eI1, eJ1, k0 + 16);
        }

        float s0 = 0.f, s1 = 0.f;
        #pragma unroll
        for (int nt = 0; nt < 8; nt++) {
            uint4 bb = *(const uint4*)(wb + (nt << 9));   // 4 B regs, 1 LDS.128
            float acc[4] = {0.f, 0.f, 0.f, 0.f};
            mma_e4m3(acc, fa[0][0], fa[0][1], fa[0][2], fa[0][3], bb.x, bb.y);
            mma_e4m3(acc, fa[1][0], fa[1][1], fa[1][2], fa[1][3], bb.z, bb.w);

            int h0 = (nt << 3) + (c << 1);
            float2 ab = *(const float2*)&sAb[h0];
            float2 ah = *(const float2*)&sAth[h0];
            s0 += fmaxf(acc[0] + ab.x, 0.f) * ah.x
                + fmaxf(acc[1] + ab.y, 0.f) * ah.y;
            s1 += fmaxf(acc[2] + ab.x, 0.f) * ah.x
                + fmaxf(acc[3] + ab.y, 0.f) * ah.y;
        }
        // descale 2^-14, quad reduce, mask padded slots
        s0 += __shfl_xor_sync(0xffffffffu, s0, 1);
        s0 += __shfl_xor_sync(0xffffffffu, s0, 2);
        s1 += __shfl_xor_sync(0xffffffffu, s1, 1);
        s1 += __shfl_xor_sync(0xffffffffu, s1, 2);
        s0 = (p0 < NPAIR) ? s0 * 6.103515625e-05f : 0.f;
        s1 = (p1 < NPAIR) ? s1 * 6.103515625e-05f : 0.f;

        // fused pooling from fp8 A regs (VV*256), accumulate in half2
        __half2 s0h = __half2half2(__float2half_rn(s0));
        __half2 s1h = __half2half2(__float2half_rn(s1));
        #pragma unroll
        for (int u = 0; u < 2; u++) {
            int sA = (u << 1) << 1;        // pk index base for seg 2u
            int sB = ((u << 1) + 1) << 1;  // seg 2u+1
            pk2[sA]     = __hfma2(cvt_f16x2_e4m3x2((unsigned short)(fa[u][0] & 0xffffu)), s0h, pk2[sA]);
            pk2[sA + 1] = __hfma2(cvt_f16x2_e4m3x2((unsigned short)(fa[u][0] >> 16)),     s0h, pk2[sA + 1]);
            pk2[sA]     = __hfma2(cvt_f16x2_e4m3x2((unsigned short)(fa[u][1] & 0xffffu)), s1h, pk2[sA]);
            pk2[sA + 1] = __hfma2(cvt_f16x2_e4m3x2((unsigned short)(fa[u][1] >> 16)),     s1h, pk2[sA + 1]);
            pk2[sB]     = __hfma2(cvt_f16x2_e4m3x2((unsigned short)(fa[u][2] & 0xffffu)), s0h, pk2[sB]);
            pk2[sB + 1] = __hfma2(cvt_f16x2_e4m3x2((unsigned short)(fa[u][2] >> 16)),     s0h, pk2[sB + 1]);
            pk2[sB]     = __hfma2(cvt_f16x2_e4m3x2((unsigned short)(fa[u][3] & 0xffffu)), s1h, pk2[sB]);
            pk2[sB + 1] = __hfma2(cvt_f16x2_e4m3x2((unsigned short)(fa[u][3] >> 16)),     s1h, pk2[sB + 1]);
        }
    }

    // reduce pooled over qr lanes, then atomics from lanes 0-3
    #pragma unroll
    for (int t = 0; t < 8; t++) {
        __half2 v = pk2[t];
        v = __hadd2(v, shfl_xor_h2(v, 4));
        v = __hadd2(v, shfl_xor_h2(v, 8));
        v = __hadd2(v, shfl_xor_h2(v, 16));
        pk2[t] = v;
    }
    if (L < 4) {
        #pragma unroll
        for (int s = 0; s < 4; s++)
            #pragma unroll
            for (int r = 0; r < 2; r++) {
                float2 f = __half22float2(pk2[s * 2 + r]);
                int k0 = (L << 2) + (s << 4) + (r << 1);
                atomicAdd(&sPooled[k0],     f.x);
                atomicAdd(&sPooled[k0 + 1], f.y);
            }
    }
    __syncthreads();

    if (w == 0) {
        float2 pv = ((const float2*)pvec)[L];
        float d = sPooled[2 * L] * pv.x + sPooled[2 * L + 1] * pv.y;
        #pragma unroll
        for (int off = 16; off; off >>= 1) d += __shfl_xor_sync(0xffffffffu, d, off);
        if (L == 0) {
            float logit = d * 0.00390625f + sFm1;   // 2^-8 descale
            out[b] = 1.f / (1.f + expf(-logit));
        }
    }
}

extern "C" void kernel_launch(void* const* d_in, const int* in_sizes, int n_in,
                              void* d_out, int out_size) {
    (void)in_sizes; (void)n_in; (void)out_size;
    const int*   x    = (const int*)  d_in[0];
    const float* emb  = (const float*)d_in[1];
    const float* at_w = (const float*)d_in[2];
    const float* at_b = (const float*)d_in[3];
    const float* at_h = (const float*)d_in[4];
    const float* pvec = (const float*)d_in[5];
    const float* w0   = (const float*)d_in[6];
    const float* w1   = (const float*)d_in[7];
    float* out = (float*)d_out;

    afm_init<<<16, 256>>>(at_w);
    afm_kernel<<<BB, NTHREADS>>>(x, emb, at_b, at_h, pvec, w0, w1, out);
}